// round 7
// baseline (speedup 1.0000x reference)
#include <cuda_runtime.h>
#include <cuda_bf16.h>

#define NN 8192
#define DD 1024
#define NP 1024
#define CAP 64
#define MARGIN_RANK 0.05f
#define PBLOCKS 128

// -------- device scratch (statically zero-initialized; g_counts/g_done reset by last block) --------
__device__ int    g_counts[NP];            // per-pair member count
__device__ float4 g_bucket[NP * CAP];      // (lev_as_float, sim_pos, sim_neg, pad)
__device__ float4 g_part_f[PBLOCKS];       // per-block (cs, ps, ns, cc_as_float)
__device__ float  g_part_rc[PBLOCKS];      // per-block rank count (as float)
__device__ int    g_done;

// ---------------------------------------------------------
// Kernel 1: warp-per-row sims + direct bucket scatter (packed float4).
// 256 thr = 8 warps = 8 rows/block, 1024 blocks.
__global__ void __launch_bounds__(256) k_sims(const float4* __restrict__ x,
                                              const float4* __restrict__ tp,
                                              const float4* __restrict__ tn,
                                              const int* __restrict__ lev,
                                              const int* __restrict__ pid) {
    int w = threadIdx.x >> 5;
    int l = threadIdx.x & 31;
    int i = (blockIdx.x << 3) + w;
    const float4* row = x + (size_t)i * (DD / 4);

    float dp = 0.f, dn = 0.f, sq = 0.f, sp2 = 0.f, sn2 = 0.f;
    #pragma unroll
    for (int k = 0; k < 8; k++) {
        int c = l + (k << 5);
        float4 v = row[c];
        float4 p = __ldg(&tp[c]);
        float4 q = __ldg(&tn[c]);
        dp  += v.x * p.x + v.y * p.y + v.z * p.z + v.w * p.w;
        dn  += v.x * q.x + v.y * q.y + v.z * q.z + v.w * q.w;
        sq  += v.x * v.x + v.y * v.y + v.z * v.z + v.w * v.w;
        sp2 += p.x * p.x + p.y * p.y + p.z * p.z + p.w * p.w;
        sn2 += q.x * q.x + q.y * q.y + q.z * q.z + q.w * q.w;
    }
    #pragma unroll
    for (int o = 16; o; o >>= 1) {
        dp  += __shfl_xor_sync(0xFFFFFFFFu, dp,  o);
        dn  += __shfl_xor_sync(0xFFFFFFFFu, dn,  o);
        sq  += __shfl_xor_sync(0xFFFFFFFFu, sq,  o);
        sp2 += __shfl_xor_sync(0xFFFFFFFFu, sp2, o);
        sn2 += __shfl_xor_sync(0xFFFFFFFFu, sn2, o);
    }
    if (l == 0) {
        float inv = rsqrtf(sq);
        float spv = dp * inv * rsqrtf(sp2);
        float snv = dn * inv * rsqrtf(sn2);
        int p = pid[i];
        int slot = atomicAdd(&g_counts[p], 1);
        if (slot < CAP) {
            g_bucket[p * CAP + slot] = make_float4((float)lev[i], spv, snv, 0.f);
        }
    }
}

// ---------------------------------------------------------
// Kernel 2: warp-per-pair pairwise terms; per-block private partial slot;
// last-done block reduces 128 slots and composes the loss.
__global__ void __launch_bounds__(256) k_pairs(float* __restrict__ out) {
    int w = threadIdx.x >> 5;
    int l = threadIdx.x & 31;
    int tid = threadIdx.x;
    int p = (blockIdx.x << 3) + w;

    __shared__ float smlev[8][CAP];
    __shared__ float smsp[8][CAP];
    __shared__ float smsn[8][CAP];

    int n = __ldcg(&g_counts[p]);        // produced by previous launch
    if (n > CAP) n = CAP;                // statistically impossible to exceed

    for (int k = l; k < n; k += 32) {
        float4 e = g_bucket[p * CAP + k];   // one LDG.128 per entry
        smlev[w][k] = e.x;
        smsp[w][k]  = e.y;
        smsn[w][k]  = e.z;
    }
    __syncwarp();

    float cs = 0.f, ps = 0.f, ns = 0.f;
    int cc = 0, rc = 0;
    for (int boff = 0; boff < n; boff += 32) {
        int bl = boff + l;
        if (bl < n) {
            float lb  = smlev[w][bl];
            float spb = smsp[w][bl];
            float snb = smsn[w][bl];
            for (int a = 0; a < n; a++) {
                float la = smlev[w][a];
                float spa = smsp[w][a], sna = smsn[w][a];
                if (bl != a) {
                    if (la == lb) {
                        if (a < bl) {
                            cs += fabsf(spa - spb) + fabsf(sna - snb);
                            cc++;
                        }
                    } else if (la < lb) {
                        ps += fmaxf(MARGIN_RANK - (spa - spb), 0.f);
                        ns += fmaxf(MARGIN_RANK + (sna - snb), 0.f);
                        rc++;
                    }
                }
            }
        }
    }

    // warp reduce
    #pragma unroll
    for (int o = 16; o; o >>= 1) {
        cs += __shfl_xor_sync(0xFFFFFFFFu, cs, o);
        ps += __shfl_xor_sync(0xFFFFFFFFu, ps, o);
        ns += __shfl_xor_sync(0xFFFFFFFFu, ns, o);
        cc += __shfl_xor_sync(0xFFFFFFFFu, cc, o);
        rc += __shfl_xor_sync(0xFFFFFFFFu, rc, o);
    }

    // block reduce in smem
    __shared__ float bcs[8], bps[8], bns[8];
    __shared__ int   bcc[8], brc[8];
    __shared__ int   is_last;
    if (l == 0) { bcs[w] = cs; bps[w] = ps; bns[w] = ns; bcc[w] = cc; brc[w] = rc; }
    __syncthreads();

    if (tid == 0) {
        float CS = 0.f, PS = 0.f, NS = 0.f;
        int CC = 0, RC = 0;
        #pragma unroll
        for (int k = 0; k < 8; k++) { CS += bcs[k]; PS += bps[k]; NS += bns[k]; CC += bcc[k]; RC += brc[k]; }
        // private slot: no contention, plain wide stores
        g_part_f[blockIdx.x]  = make_float4(CS, PS, NS, (float)CC);
        g_part_rc[blockIdx.x] = (float)RC;
        __threadfence();
        int t = atomicAdd(&g_done, 1);
        is_last = (t == PBLOCKS - 1) ? 1 : 0;
    }
    __syncthreads();

    if (is_last) {
        // coalesced: thread k owns block k's partial (PBLOCKS == 128 <= 256 thr)
        float cs2 = 0.f, ps2 = 0.f, ns2 = 0.f, cc2 = 0.f, rc2 = 0.f;
        if (tid < PBLOCKS) {
            float4 f = g_part_f[tid];
            cs2 = f.x; ps2 = f.y; ns2 = f.z; cc2 = f.w;
            rc2 = g_part_rc[tid];
        }
        #pragma unroll
        for (int o = 16; o; o >>= 1) {
            cs2 += __shfl_xor_sync(0xFFFFFFFFu, cs2, o);
            ps2 += __shfl_xor_sync(0xFFFFFFFFu, ps2, o);
            ns2 += __shfl_xor_sync(0xFFFFFFFFu, ns2, o);
            cc2 += __shfl_xor_sync(0xFFFFFFFFu, cc2, o);
            rc2 += __shfl_xor_sync(0xFFFFFFFFu, rc2, o);
        }
        __shared__ float fcs[4], fps[4], fns[4], fcc[4], frc[4];
        if (l == 0 && w < 4) { fcs[w] = cs2; fps[w] = ps2; fns[w] = ns2; fcc[w] = cc2; frc[w] = rc2; }
        __syncthreads();
        if (tid == 0) {
            float CS = fcs[0] + fcs[1] + fcs[2] + fcs[3];
            float PS = fps[0] + fps[1] + fps[2] + fps[3];
            float NS = fns[0] + fns[1] + fns[2] + fns[3];
            float CC = fcc[0] + fcc[1] + fcc[2] + fcc[3];
            float RC = frc[0] + frc[1] + frc[2] + frc[3];
            float loss_cons = (CC > 0.f) ? CS / (2.0f * CC) : 0.0f;
            float loss_pos  = (RC > 0.f) ? PS / RC : 0.0f;
            float loss_neg  = (RC > 0.f) ? NS / RC : 0.0f;
            out[0] = loss_cons + loss_pos + loss_neg;
            g_done = 0;  // reset for next graph replay
        }
        // reset counts for next replay
        for (int k = tid; k < NP; k += 256) g_counts[k] = 0;
    }
}

// ---------------------------------------------------------
extern "C" void kernel_launch(void* const* d_in, const int* in_sizes, int n_in,
                              void* d_out, int out_size) {
    const float* img = (const float*)d_in[0];   // [N, D]
    const float* tp  = (const float*)d_in[1];   // [D]
    const float* tn  = (const float*)d_in[2];   // [D]
    const int*   lev = (const int*)d_in[3];     // [N]
    const int*   pid = (const int*)d_in[4];     // [N]
    float* out = (float*)d_out;

    k_sims<<<NN / 8, 256>>>((const float4*)img, (const float4*)tp, (const float4*)tn, lev, pid);
    k_pairs<<<PBLOCKS, 256>>>(out);
}